// round 11
// baseline (speedup 1.0000x reference)
#include <cuda_runtime.h>
#include <cuda_fp16.h>
#include <cstdint>

// Problem constants: B=4, S=256, D_MODEL=2048, H=256, HEAD_DIM=8
#define TOKENS   1024
#define DM       2048
#define NHEADS   256

// ---------------------------------------------------------------------------
// Scratch (__device__ globals; allocation-free rule)
// ---------------------------------------------------------------------------
__device__ __align__(16) float  g_q[TOKENS * DM];
__device__ __align__(16) float  g_k[TOKENS * DM];
__device__ __align__(16) float  g_v[TOKENS * DM];
__device__ __align__(16) __half g_ah[TOKENS * DM];      // attn out (fp16)
__device__ __align__(16) __half g_xh[TOKENS * DM];      // x (fp16)
__device__ __align__(16) __half g_wth[4 * DM * DM];     // W^T fp16 (Wq,Wk,Wv,Wo), [N][K]

__device__ __forceinline__ void cp16(uint32_t saddr, const void* gptr) {
    asm volatile("cp.async.cg.shared.global [%0], [%1], 16;\n" :: "r"(saddr), "l"(gptr));
}
__device__ __forceinline__ void mma_f16(float* c, const uint32_t* a, const uint32_t* b) {
    asm volatile(
        "mma.sync.aligned.m16n8k16.row.col.f32.f16.f16.f32 "
        "{%0,%1,%2,%3}, {%4,%5,%6,%7}, {%8,%9}, {%0,%1,%2,%3};"
        : "+f"(c[0]), "+f"(c[1]), "+f"(c[2]), "+f"(c[3])
        : "r"(a[0]), "r"(a[1]), "r"(a[2]), "r"(a[3]), "r"(b[0]), "r"(b[1]));
}
__device__ __forceinline__ void ldsm4(uint32_t& r0, uint32_t& r1, uint32_t& r2, uint32_t& r3,
                                      uint32_t addr) {
    asm volatile("ldmatrix.sync.aligned.m8n8.x4.shared.b16 {%0,%1,%2,%3}, [%4];"
                 : "=r"(r0), "=r"(r1), "=r"(r2), "=r"(r3) : "r"(addr));
}

// packed f32x2 helpers (base-ISA sm_100+)
__device__ __forceinline__ uint64_t pk2(float lo, float hi) {
    uint64_t r; asm("mov.b64 %0, {%1, %2};" : "=l"(r) : "f"(lo), "f"(hi)); return r;
}
__device__ __forceinline__ void up2(uint64_t v, float& lo, float& hi) {
    asm("mov.b64 {%0, %1}, %2;" : "=f"(lo), "=f"(hi) : "l"(v));
}
__device__ __forceinline__ uint64_t fma2(uint64_t a, uint64_t b, uint64_t c) {
    uint64_t d; asm("fma.rn.f32x2 %0, %1, %2, %3;" : "=l"(d) : "l"(a), "l"(b), "l"(c)); return d;
}
__device__ __forceinline__ uint64_t mul2(uint64_t a, uint64_t b) {
    uint64_t d; asm("mul.rn.f32x2 %0, %1, %2;" : "=l"(d) : "l"(a), "l"(b)); return d;
}
__device__ __forceinline__ float ex2f(float x) {
    float y; asm("ex2.approx.f32 %0, %1;" : "=f"(y) : "f"(x)); return y;
}

// ---------------------------------------------------------------------------
// FP16 mma.sync GEMM: C(f32)[1024,2048] = A(h)[M,K] @ Wt(h)[N,K]^T + bias
// CTA tile 128x64x32 (fine-grained for wave balance), 8 warps 4m x 2n,
// warp tile 32x32, 4-stage cp.async ring, ldmatrix loads, direct-STG epilogue.
// ---------------------------------------------------------------------------
#define BM 128
#define BN 64
#define BK 32
#define NS 4
#define NK (DM / BK)              // 64
#define SAH 40                    // halves per row (80 B; LDSM conflict-free)
#define A_H (BM * SAH)            // 5120 halves
#define B_H (BN * SAH)            // 2560 halves
#define STG_B ((A_H + B_H) * 2)   // 15360 bytes
#define GEMM_SMEM (NS * STG_B)    // 61440

__global__ void __launch_bounds__(256, 2) gemm_h(
    const __half* __restrict__ A,
    const __half* __restrict__ T0, const __half* __restrict__ T1, const __half* __restrict__ T2,
    const float* __restrict__ b0, const float* __restrict__ b1, const float* __restrict__ b2,
    float* __restrict__ C0, float* __restrict__ C1, float* __restrict__ C2)
{
    extern __shared__ char smem[];
    uint32_t sbase;
    asm("{ .reg .u64 t; cvta.to.shared.u64 t, %1; cvt.u32.u64 %0, t; }" : "=r"(sbase) : "l"(smem));

    const int z = blockIdx.z;
    const __half* Wt  = (z == 0) ? T0 : (z == 1) ? T1 : T2;
    const float* bias = (z == 0) ? b0 : (z == 1) ? b1 : b2;
    float*       C    = (z == 0) ? C0 : (z == 1) ? C1 : C2;

    const int tid  = threadIdx.x;
    const int lane = tid & 31;
    const int g    = lane >> 2;
    const int t    = lane & 3;
    const int warp = tid >> 5;
    const int mrow0 = (warp >> 1) * 32;      // 4 warps along m
    const int ncol0 = (warp & 1) * 32;       // 2 warps along n
    const int bm = blockIdx.y * BM;
    const int bn = blockIdx.x * BN;

    const uint32_t a_lm = (uint32_t)((mrow0 + (lane & 15)) * SAH + (lane >> 4) * 8);
    const uint32_t b_lm = (uint32_t)((ncol0 + (lane >> 4) * 8 + (lane & 7)) * SAH
                                     + ((lane >> 3) & 1) * 8);

    float acc[2][4][4];
#pragma unroll
    for (int i = 0; i < 2; i++)
#pragma unroll
        for (int j = 0; j < 4; j++)
#pragma unroll
            for (int e = 0; e < 4; e++) acc[i][j][e] = 0.0f;

    auto fill = [&](int it) {
        const uint32_t ab = sbase + (uint32_t)((it % NS) * STG_B);
        const uint32_t bb = ab + A_H * 2;
        const int kt = it * BK;
        const __half* Ag = A  + (size_t)bm * DM + kt;
        const __half* Bg = Wt + (size_t)bn * DM + kt;
#pragma unroll
        for (int l = 0; l < 2; l++) {          // A: 128 rows x 4 chunks(16B)
            int i = tid + l * 256;
            int r = i >> 2, c = i & 3;
            cp16(ab + (uint32_t)(r * 80 + c * 16), Ag + (size_t)r * DM + c * 8);
        }
        {                                      // B: 64 rows x 4 chunks = 1/thread
            int r = tid >> 2, c = tid & 3;
            cp16(bb + (uint32_t)(r * 80 + c * 16), Bg + (size_t)r * DM + c * 8);
        }
        asm volatile("cp.async.commit_group;" ::: "memory");
    };

    fill(0); fill(1); fill(2);

#pragma unroll 1
    for (int it = 0; it < NK; it++) {
        asm volatile("cp.async.wait_group 2;" ::: "memory");
        __syncthreads();
        if (it + 3 < NK) fill(it + 3);
        else asm volatile("cp.async.commit_group;" ::: "memory");

        const uint32_t abase = sbase + (uint32_t)((it % NS) * STG_B);
        const uint32_t bbase = abase + A_H * 2;

#pragma unroll
        for (int kk = 0; kk < BK; kk += 16) {
            uint32_t af[2][4], bf[4][2];
#pragma unroll
            for (int mi = 0; mi < 2; mi++)
                ldsm4(af[mi][0], af[mi][1], af[mi][2], af[mi][3],
                      abase + (a_lm + (uint32_t)(mi * 16 * SAH + kk)) * 2);
#pragma unroll
            for (int p = 0; p < 2; p++)
                ldsm4(bf[2*p][0], bf[2*p][1], bf[2*p+1][0], bf[2*p+1][1],
                      bbase + (b_lm + (uint32_t)(p * 16 * SAH + kk)) * 2);
#pragma unroll
            for (int mi = 0; mi < 2; mi++)
#pragma unroll
                for (int nj = 0; nj < 4; nj++)
                    mma_f16(acc[mi][nj], af[mi], bf[nj]);
        }
    }

    // ---- direct-store epilogue: fused bias, STG.64 per acc pair ----
    float2 bb2[4];
#pragma unroll
    for (int nj = 0; nj < 4; nj++)
        bb2[nj] = *reinterpret_cast<const float2*>(&bias[bn + ncol0 + nj * 8 + 2 * t]);

#pragma unroll
    for (int mi = 0; mi < 2; mi++) {
        const int r0 = bm + mrow0 + mi * 16 + g;
        float* crow0 = C + (size_t)r0 * DM;
        float* crow1 = crow0 + 8 * DM;
#pragma unroll
        for (int nj = 0; nj < 4; nj++) {
            const int c = bn + ncol0 + nj * 8 + 2 * t;
            *reinterpret_cast<float2*>(&crow0[c]) =
                make_float2(acc[mi][nj][0] + bb2[nj].x, acc[mi][nj][1] + bb2[nj].y);
            *reinterpret_cast<float2*>(&crow1[c]) =
                make_float2(acc[mi][nj][2] + bb2[nj].x, acc[mi][nj][3] + bb2[nj].y);
        }
    }
}

// ---------------------------------------------------------------------------
// Prep: x -> half;  W[k][n] f32 -> Wt[n][k] half (transpose + convert)
// ---------------------------------------------------------------------------
__global__ void xcvt_kernel(const float* __restrict__ src, __half* __restrict__ dst, int n4)
{
    int i = blockIdx.x * blockDim.x + threadIdx.x;
    if (i < n4) {
        float4 v = reinterpret_cast<const float4*>(src)[i];
        __half2* d = reinterpret_cast<__half2*>(dst) + 2 * i;
        d[0] = __floats2half2_rn(v.x, v.y);
        d[1] = __floats2half2_rn(v.z, v.w);
    }
}

__global__ void wtrans_kernel(
    const float* __restrict__ W0, const float* __restrict__ W1,
    const float* __restrict__ W2, const float* __restrict__ W3)
{
    __shared__ float tsm[32][33];
    const int zz = blockIdx.z;
    const float* src = (zz == 0) ? W0 : (zz == 1) ? W1 : (zz == 2) ? W2 : W3;
    __half* dst = g_wth + (size_t)zz * DM * DM;

    const int n0 = blockIdx.x * 32;
    const int k0 = blockIdx.y * 32;
    const int tid = threadIdx.x;
    const int tx = tid & 31, ty = tid >> 5;

#pragma unroll
    for (int j = ty; j < 32; j += 8)
        tsm[j][tx] = src[(size_t)(k0 + j) * DM + n0 + tx];
    __syncthreads();

#pragma unroll
    for (int idx = tid; idx < 32 * 16; idx += 256) {
        int r = idx >> 4, c = idx & 15;
        __half2 h = __floats2half2_rn(tsm[2 * c][r], tsm[2 * c + 1][r]);
        *reinterpret_cast<__half2*>(&dst[(size_t)(n0 + r) * DM + k0 + 2 * c]) = h;
    }
}

// ---------------------------------------------------------------------------
// Per-token head-mixing attention: 128 threads, 2 heads/thread, f32x2 + ex2.
// (Round-9 version: best measured at 60.1 us; split-g variant regressed.)
// ---------------------------------------------------------------------------
__global__ void __launch_bounds__(128) attn_kernel()
{
    const int tk = blockIdx.x;
    const int h0 = threadIdx.x;
    const int h1 = h0 + 128;

    __shared__ uint64_t sk[NHEADS * 4];
    __shared__ uint64_t sv[NHEADS * 4];

    const uint64_t* qp = reinterpret_cast<const uint64_t*>(&g_q[(size_t)tk * DM]);
    const uint64_t* kp = reinterpret_cast<const uint64_t*>(&g_k[(size_t)tk * DM]);
    const uint64_t* vp = reinterpret_cast<const uint64_t*>(&g_v[(size_t)tk * DM]);

    const float scale = 0.35355339059327373f * 1.4426950408889634f;  // log2e/sqrt(8)
    const uint64_t scl = pk2(scale, scale);

    uint64_t qa[4], qb[4];
#pragma unroll
    for (int j = 0; j < 4; j++) {
        sk[h0 * 4 + j] = kp[h0 * 4 + j];
        sk[h1 * 4 + j] = kp[h1 * 4 + j];
        sv[h0 * 4 + j] = vp[h0 * 4 + j];
        sv[h1 * 4 + j] = vp[h1 * 4 + j];
        qa[j] = mul2(qp[h0 * 4 + j], scl);
        qb[j] = mul2(qp[h1 * 4 + j], scl);
    }
    __syncthreads();

    float lsa = 0.0f, lsb = 0.0f;
    uint64_t aa[4] = {0ull, 0ull, 0ull, 0ull};
    uint64_t ab[4] = {0ull, 0ull, 0ull, 0ull};

#pragma unroll 4
    for (int gg = 0; gg < NHEADS; gg++) {
        uint64_t k0 = sk[gg * 4 + 0], k1 = sk[gg * 4 + 1];
        uint64_t k2 = sk[gg * 4 + 2], k3 = sk[gg * 4 + 3];

        uint64_t pa = mul2(qa[0], k0);
        pa = fma2(qa[1], k1, pa);
        pa = fma2(qa[2], k2, pa);
        pa = fma2(qa[3], k3, pa);
        uint64_t pb = mul2(qb[0], k0);
        pb = fma2(qb[1], k1, pb);
        pb = fma2(qb[2], k2, pb);
        pb = fma2(qb[3], k3, pb);

        float la, ha, lb, hb;
        up2(pa, la, ha);
        up2(pb, lb, hb);
        float ea = ex2f(la + ha);      // base-2 exp; log2e folded into q scale
        float eb = ex2f(lb + hb);
        lsa += ea;
        lsb += eb;

        uint64_t v0 = sv[gg * 4 + 0], v1 = sv[gg * 4 + 1];
        uint64_t v2 = sv[gg * 4 + 2], v3 = sv[gg * 4 + 3];
        uint64_t pea = pk2(ea, ea), peb = pk2(eb, eb);
        aa[0] = fma2(pea, v0, aa[0]);  aa[1] = fma2(pea, v1, aa[1]);
        aa[2] = fma2(pea, v2, aa[2]);  aa[3] = fma2(pea, v3, aa[3]);
        ab[0] = fma2(peb, v0, ab[0]);  ab[1] = fma2(peb, v1, ab[1]);
        ab[2] = fma2(peb, v2, ab[2]);  ab[3] = fma2(peb, v3, ab[3]);
    }

    const float inva = 1.0f / lsa;
    const float invb = 1.0f / lsb;
    __half2* oa = reinterpret_cast<__half2*>(&g_ah[(size_t)tk * DM + h0 * 8]);
    __half2* ob = reinterpret_cast<__half2*>(&g_ah[(size_t)tk * DM + h1 * 8]);
#pragma unroll
    for (int j = 0; j < 4; j++) {
        float lo, hi;
        up2(aa[j], lo, hi);
        oa[j] = __floats2half2_rn(lo * inva, hi * inva);
        up2(ab[j], lo, hi);
        ob[j] = __floats2half2_rn(lo * invb, hi * invb);
    }
}

// ---------------------------------------------------------------------------
// Launch
// ---------------------------------------------------------------------------
extern "C" void kernel_launch(void* const* d_in, const int* in_sizes, int n_in,
                              void* d_out, int out_size)
{
    const float* x  = (const float*)d_in[0];
    // d_in[1] = phase_shift: cos^2+sin^2 cancels analytically; unused.
    const float* Wq = (const float*)d_in[2];
    const float* bq = (const float*)d_in[3];
    const float* Wk = (const float*)d_in[4];
    const float* bk = (const float*)d_in[5];
    const float* Wv = (const float*)d_in[6];
    const float* bv = (const float*)d_in[7];
    const float* Wo = (const float*)d_in[8];
    const float* bo = (const float*)d_in[9];
    float* out = (float*)d_out;

    float *q_p, *k_p, *v_p;
    __half *ah_p, *xh_p, *wt_p;
    cudaGetSymbolAddress((void**)&q_p,  g_q);
    cudaGetSymbolAddress((void**)&k_p,  g_k);
    cudaGetSymbolAddress((void**)&v_p,  g_v);
    cudaGetSymbolAddress((void**)&ah_p, g_ah);
    cudaGetSymbolAddress((void**)&xh_p, g_xh);
    cudaGetSymbolAddress((void**)&wt_p, g_wth);

    cudaFuncSetAttribute(gemm_h, cudaFuncAttributeMaxDynamicSharedMemorySize, GEMM_SMEM);

    const size_t WSZ = (size_t)DM * DM;
    const int nx4 = TOKENS * DM / 4;
    xcvt_kernel<<<(nx4 + 255) / 256, 256>>>(x, xh_p, nx4);
    wtrans_kernel<<<dim3(DM / 32, DM / 32, 4), 256>>>(Wq, Wk, Wv, Wo);

    dim3 gQKV(DM / BN, TOKENS / BM, 3);    // (32, 8, 3) = 768 CTAs
    gemm_h<<<gQKV, 256, GEMM_SMEM>>>(xh_p,
        wt_p, wt_p + WSZ, wt_p + 2 * WSZ,
        bq, bk, bv, q_p, k_p, v_p);

    attn_kernel<<<TOKENS, 128>>>();

    dim3 gO(DM / BN, TOKENS / BM, 1);      // (32, 8, 1) = 256 CTAs
    gemm_h<<<gO, 256, GEMM_SMEM>>>(ah_p,
        wt_p + 3 * WSZ, wt_p + 3 * WSZ, wt_p + 3 * WSZ,
        bo, bo, bo, out, out, out);
}

// round 12
// speedup vs baseline: 1.5896x; 1.5896x over previous
#include <cuda_runtime.h>
#include <cuda_fp16.h>
#include <cstdint>

// Problem constants: B=4, S=256, D_MODEL=2048, H=256, HEAD_DIM=8
#define TOKENS   1024
#define DM       2048
#define NHEADS   256

// ---------------------------------------------------------------------------
// Scratch (__device__ globals; allocation-free rule)
// ---------------------------------------------------------------------------
__device__ __align__(16) float  g_q[TOKENS * DM];
__device__ __align__(16) float  g_k[TOKENS * DM];
__device__ __align__(16) float  g_v[TOKENS * DM];
__device__ __align__(16) __half g_ah[TOKENS * DM];      // attn out (fp16)
__device__ __align__(16) __half g_xh[TOKENS * DM];      // x (fp16)
__device__ __align__(16) __half g_wth[4 * DM * DM];     // W^T fp16 (Wq,Wk,Wv,Wo), [N][K]

__device__ __forceinline__ void cp16(uint32_t saddr, const void* gptr) {
    asm volatile("cp.async.cg.shared.global [%0], [%1], 16;\n" :: "r"(saddr), "l"(gptr));
}
__device__ __forceinline__ void mma_f16(float* c, const uint32_t* a, const uint32_t* b) {
    asm volatile(
        "mma.sync.aligned.m16n8k16.row.col.f32.f16.f16.f32 "
        "{%0,%1,%2,%3}, {%4,%5,%6,%7}, {%8,%9}, {%0,%1,%2,%3};"
        : "+f"(c[0]), "+f"(c[1]), "+f"(c[2]), "+f"(c[3])
        : "r"(a[0]), "r"(a[1]), "r"(a[2]), "r"(a[3]), "r"(b[0]), "r"(b[1]));
}
__device__ __forceinline__ void ldsm4(uint32_t& r0, uint32_t& r1, uint32_t& r2, uint32_t& r3,
                                      uint32_t addr) {
    asm volatile("ldmatrix.sync.aligned.m8n8.x4.shared.b16 {%0,%1,%2,%3}, [%4];"
                 : "=r"(r0), "=r"(r1), "=r"(r2), "=r"(r3) : "r"(addr));
}

// packed f32x2 helpers (base-ISA sm_100+)
__device__ __forceinline__ uint64_t pk2(float lo, float hi) {
    uint64_t r; asm("mov.b64 %0, {%1, %2};" : "=l"(r) : "f"(lo), "f"(hi)); return r;
}
__device__ __forceinline__ uint64_t pk2u(uint32_t lo, uint32_t hi) {
    uint64_t r; asm("mov.b64 %0, {%1, %2};" : "=l"(r) : "r"(lo), "r"(hi)); return r;
}
__device__ __forceinline__ void up2(uint64_t v, float& lo, float& hi) {
    asm("mov.b64 {%0, %1}, %2;" : "=f"(lo), "=f"(hi) : "l"(v));
}
__device__ __forceinline__ uint64_t fma2(uint64_t a, uint64_t b, uint64_t c) {
    uint64_t d; asm("fma.rn.f32x2 %0, %1, %2, %3;" : "=l"(d) : "l"(a), "l"(b), "l"(c)); return d;
}
__device__ __forceinline__ uint64_t mul2(uint64_t a, uint64_t b) {
    uint64_t d; asm("mul.rn.f32x2 %0, %1, %2;" : "=l"(d) : "l"(a), "l"(b)); return d;
}
__device__ __forceinline__ float ex2f(float x) {
    float y; asm("ex2.approx.f32 %0, %1;" : "=f"(y) : "f"(x)); return y;
}

// ---------------------------------------------------------------------------
// FP16 mma.sync GEMM (templated BN): C(f32) = A(h)[M,K] @ Wt(h)[N,K]^T + bias
// BM=128, BK=32, 4-stage cp.async ring, ldmatrix fragment loads.
// BNt=128: 8 warps 2x4 (warp 64x32).  BNt=64: 8 warps 4x2 (warp 32x32).
// (Round-9 configuration: best measured 233.6 us.)
// ---------------------------------------------------------------------------
#define BM 128
#define BK 32
#define NS 4
#define NK (DM / BK)              // 64
#define SAH 40                    // halves per row (80 B, LDSM conflict-free)
#define A_H (BM * SAH)            // 5120 halves

template <int BNt>
__global__ void __launch_bounds__(256, 2) gemm_h(
    const __half* __restrict__ A,
    const __half* __restrict__ T0, const __half* __restrict__ T1, const __half* __restrict__ T2,
    const float* __restrict__ b0, const float* __restrict__ b1, const float* __restrict__ b2,
    float* __restrict__ C0, float* __restrict__ C1, float* __restrict__ C2)
{
    constexpr int WCN   = BNt / 32;
    constexpr int MI    = (BNt == 128) ? 4 : 2;
    constexpr int B_H   = BNt * SAH;
    constexpr int STG_B = (A_H + B_H) * 2;
    constexpr int BCH   = BNt * 4 / 256;
    constexpr int SCt   = BNt + 4;

    extern __shared__ char smem[];
    uint32_t sbase;
    asm("{ .reg .u64 t; cvta.to.shared.u64 t, %1; cvt.u32.u64 %0, t; }" : "=r"(sbase) : "l"(smem));

    const int z = blockIdx.z;
    const __half* Wt  = (z == 0) ? T0 : (z == 1) ? T1 : T2;
    const float* bias = (z == 0) ? b0 : (z == 1) ? b1 : b2;
    float*       C    = (z == 0) ? C0 : (z == 1) ? C1 : C2;

    const int tid  = threadIdx.x;
    const int lane = tid & 31;
    const int g    = lane >> 2;
    const int t    = lane & 3;
    const int warp = tid >> 5;
    const int mrow0 = (warp / WCN) * (MI * 16);
    const int ncol0 = (warp % WCN) * 32;
    const int bm = blockIdx.y * BM;
    const int bn = blockIdx.x * BNt;

    const uint32_t a_lm = (uint32_t)((mrow0 + (lane & 15)) * SAH + (lane >> 4) * 8);
    const uint32_t b_lm = (uint32_t)((ncol0 + (lane >> 4) * 8 + (lane & 7)) * SAH
                                     + ((lane >> 3) & 1) * 8);

    float acc[MI][4][4];
#pragma unroll
    for (int i = 0; i < MI; i++)
#pragma unroll
        for (int j = 0; j < 4; j++)
#pragma unroll
            for (int e = 0; e < 4; e++) acc[i][j][e] = 0.0f;

    auto fill = [&](int it) {
        const uint32_t ab = sbase + (uint32_t)((it % NS) * STG_B);
        const uint32_t bb = ab + A_H * 2;
        const int kt = it * BK;
        const __half* Ag = A  + (size_t)bm * DM + kt;
        const __half* Bg = Wt + (size_t)bn * DM + kt;
#pragma unroll
        for (int l = 0; l < 2; l++) {
            int i = tid + l * 256;
            int r = i >> 2, c = i & 3;
            cp16(ab + (uint32_t)(r * 80 + c * 16), Ag + (size_t)r * DM + c * 8);
        }
#pragma unroll
        for (int l = 0; l < BCH; l++) {
            int i = tid + l * 256;
            int r = i >> 2, c = i & 3;
            cp16(bb + (uint32_t)(r * 80 + c * 16), Bg + (size_t)r * DM + c * 8);
        }
        asm volatile("cp.async.commit_group;" ::: "memory");
    };

    fill(0); fill(1); fill(2);

#pragma unroll 1
    for (int it = 0; it < NK; it++) {
        asm volatile("cp.async.wait_group 2;" ::: "memory");
        __syncthreads();
        if (it + 3 < NK) fill(it + 3);
        else asm volatile("cp.async.commit_group;" ::: "memory");

        const uint32_t abase = sbase + (uint32_t)((it % NS) * STG_B);
        const uint32_t bbase = abase + A_H * 2;

#pragma unroll
        for (int kk = 0; kk < BK; kk += 16) {
            uint32_t af[MI][4], bf[4][2];
#pragma unroll
            for (int mi = 0; mi < MI; mi++)
                ldsm4(af[mi][0], af[mi][1], af[mi][2], af[mi][3],
                      abase + (a_lm + (uint32_t)(mi * 16 * SAH + kk)) * 2);
#pragma unroll
            for (int p = 0; p < 2; p++)
                ldsm4(bf[2*p][0], bf[2*p][1], bf[2*p+1][0], bf[2*p+1][1],
                      bbase + (b_lm + (uint32_t)(p * 16 * SAH + kk)) * 2);
#pragma unroll
            for (int mi = 0; mi < MI; mi++)
#pragma unroll
                for (int nj = 0; nj < 4; nj++)
                    mma_f16(acc[mi][nj], af[mi], bf[nj]);
        }
    }

    // ---- epilogue: stage accumulators to smem, fused bias, coalesced stores ----
    __syncthreads();
    float* Cs = reinterpret_cast<float*>(smem);
#pragma unroll
    for (int mi = 0; mi < MI; mi++) {
        const int r0 = mrow0 + mi * 16 + g;
#pragma unroll
        for (int nj = 0; nj < 4; nj++) {
            const int c = ncol0 + nj * 8 + 2 * t;
            *reinterpret_cast<float2*>(&Cs[(r0)     * SCt + c]) = make_float2(acc[mi][nj][0], acc[mi][nj][1]);
            *reinterpret_cast<float2*>(&Cs[(r0 + 8) * SCt + c]) = make_float2(acc[mi][nj][2], acc[mi][nj][3]);
        }
    }
    __syncthreads();

#pragma unroll
    for (int l = 0; l < BM * BNt / 4 / 256; l++) {
        int i = tid + l * 256;
        int r = i / (BNt / 4), c = (i % (BNt / 4)) * 4;
        float4 v  = *reinterpret_cast<float4*>(&Cs[r * SCt + c]);
        float4 bb = *reinterpret_cast<const float4*>(&bias[bn + c]);
        v.x += bb.x; v.y += bb.y; v.z += bb.z; v.w += bb.w;
        *reinterpret_cast<float4*>(&C[(size_t)(bm + r) * DM + bn + c]) = v;
    }
}

// ---------------------------------------------------------------------------
// Prep: x -> half;  W[k][n] f32 -> Wt[n][k] half (transpose + convert)
// ---------------------------------------------------------------------------
__global__ void xcvt_kernel(const float* __restrict__ src, __half* __restrict__ dst, int n4)
{
    int i = blockIdx.x * blockDim.x + threadIdx.x;
    if (i < n4) {
        float4 v = reinterpret_cast<const float4*>(src)[i];
        __half2* d = reinterpret_cast<__half2*>(dst) + 2 * i;
        d[0] = __floats2half2_rn(v.x, v.y);
        d[1] = __floats2half2_rn(v.z, v.w);
    }
}

__global__ void wtrans_kernel(
    const float* __restrict__ W0, const float* __restrict__ W1,
    const float* __restrict__ W2, const float* __restrict__ W3)
{
    __shared__ float tsm[32][33];
    const int zz = blockIdx.z;
    const float* src = (zz == 0) ? W0 : (zz == 1) ? W1 : (zz == 2) ? W2 : W3;
    __half* dst = g_wth + (size_t)zz * DM * DM;

    const int n0 = blockIdx.x * 32;
    const int k0 = blockIdx.y * 32;
    const int tid = threadIdx.x;
    const int tx = tid & 31, ty = tid >> 5;

#pragma unroll
    for (int j = ty; j < 32; j += 8)
        tsm[j][tx] = src[(size_t)(k0 + j) * DM + n0 + tx];
    __syncthreads();

#pragma unroll
    for (int idx = tid; idx < 32 * 16; idx += 256) {
        int r = idx >> 4, c = idx & 15;
        __half2 h = __floats2half2_rn(tsm[2 * c][r], tsm[2 * c + 1][r]);
        *reinterpret_cast<__half2*>(&dst[(size_t)(n0 + r) * DM + k0 + 2 * c]) = h;
    }
}

// ---------------------------------------------------------------------------
// Per-token head-mixing attention: 128 threads, 2 heads/thread, f32x2 + ex2.
// k/v staged in smem as uint4 -> 4x LDS.128 per iter (was 8x LDS.64).
// ---------------------------------------------------------------------------
__global__ void __launch_bounds__(128) attn_kernel()
{
    const int tk = blockIdx.x;
    const int h0 = threadIdx.x;
    const int h1 = h0 + 128;

    __shared__ uint4 sk[NHEADS * 2];     // 32 B per head = 2 uint4
    __shared__ uint4 sv[NHEADS * 2];

    const uint4* qp = reinterpret_cast<const uint4*>(&g_q[(size_t)tk * DM]);
    const uint4* kp = reinterpret_cast<const uint4*>(&g_k[(size_t)tk * DM]);
    const uint4* vp = reinterpret_cast<const uint4*>(&g_v[(size_t)tk * DM]);

    const float scale = 0.35355339059327373f * 1.4426950408889634f;  // log2e/sqrt(8)
    const uint64_t scl = pk2(scale, scale);

    uint64_t qa[4], qb[4];
#pragma unroll
    for (int j = 0; j < 2; j++) {
        sk[h0 * 2 + j] = kp[h0 * 2 + j];
        sk[h1 * 2 + j] = kp[h1 * 2 + j];
        sv[h0 * 2 + j] = vp[h0 * 2 + j];
        sv[h1 * 2 + j] = vp[h1 * 2 + j];
        uint4 qv;
        qv = qp[h0 * 2 + j];
        qa[2*j]   = mul2(pk2u(qv.x, qv.y), scl);
        qa[2*j+1] = mul2(pk2u(qv.z, qv.w), scl);
        qv = qp[h1 * 2 + j];
        qb[2*j]   = mul2(pk2u(qv.x, qv.y), scl);
        qb[2*j+1] = mul2(pk2u(qv.z, qv.w), scl);
    }
    __syncthreads();

    float lsa = 0.0f, lsb = 0.0f;
    uint64_t aa[4] = {0ull, 0ull, 0ull, 0ull};
    uint64_t ab[4] = {0ull, 0ull, 0ull, 0ull};

#pragma unroll 4
    for (int gg = 0; gg < NHEADS; gg++) {
        const uint4 kv0 = sk[gg * 2];
        const uint4 kv1 = sk[gg * 2 + 1];
        const uint64_t k0 = pk2u(kv0.x, kv0.y), k1 = pk2u(kv0.z, kv0.w);
        const uint64_t k2 = pk2u(kv1.x, kv1.y), k3 = pk2u(kv1.z, kv1.w);

        uint64_t pa = mul2(qa[0], k0);
        pa = fma2(qa[1], k1, pa);
        pa = fma2(qa[2], k2, pa);
        pa = fma2(qa[3], k3, pa);
        uint64_t pb = mul2(qb[0], k0);
        pb = fma2(qb[1], k1, pb);
        pb = fma2(qb[2], k2, pb);
        pb = fma2(qb[3], k3, pb);

        float la, ha, lb, hb;
        up2(pa, la, ha);
        up2(pb, lb, hb);
        float ea = ex2f(la + ha);      // base-2 exp; log2e folded into q scale
        float eb = ex2f(lb + hb);
        lsa += ea;
        lsb += eb;

        const uint4 vv0 = sv[gg * 2];
        const uint4 vv1 = sv[gg * 2 + 1];
        const uint64_t v0 = pk2u(vv0.x, vv0.y), v1 = pk2u(vv0.z, vv0.w);
        const uint64_t v2 = pk2u(vv1.x, vv1.y), v3 = pk2u(vv1.z, vv1.w);
        const uint64_t pea = pk2(ea, ea), peb = pk2(eb, eb);
        aa[0] = fma2(pea, v0, aa[0]);  aa[1] = fma2(pea, v1, aa[1]);
        aa[2] = fma2(pea, v2, aa[2]);  aa[3] = fma2(pea, v3, aa[3]);
        ab[0] = fma2(peb, v0, ab[0]);  ab[1] = fma2(peb, v1, ab[1]);
        ab[2] = fma2(peb, v2, ab[2]);  ab[3] = fma2(peb, v3, ab[3]);
    }

    const float inva = 1.0f / lsa;
    const float invb = 1.0f / lsb;
    __half2* oa = reinterpret_cast<__half2*>(&g_ah[(size_t)tk * DM + h0 * 8]);
    __half2* ob = reinterpret_cast<__half2*>(&g_ah[(size_t)tk * DM + h1 * 8]);
#pragma unroll
    for (int j = 0; j < 4; j++) {
        float lo, hi;
        up2(aa[j], lo, hi);
        oa[j] = __floats2half2_rn(lo * inva, hi * inva);
        up2(ab[j], lo, hi);
        ob[j] = __floats2half2_rn(lo * invb, hi * invb);
    }
}

// ---------------------------------------------------------------------------
// Launch  (round-9 configuration)
// ---------------------------------------------------------------------------
extern "C" void kernel_launch(void* const* d_in, const int* in_sizes, int n_in,
                              void* d_out, int out_size)
{
    const float* x  = (const float*)d_in[0];
    // d_in[1] = phase_shift: cos^2+sin^2 cancels analytically; unused.
    const float* Wq = (const float*)d_in[2];
    const float* bq = (const float*)d_in[3];
    const float* Wk = (const float*)d_in[4];
    const float* bk = (const float*)d_in[5];
    const float* Wv = (const float*)d_in[6];
    const float* bv = (const float*)d_in[7];
    const float* Wo = (const float*)d_in[8];
    const float* bo = (const float*)d_in[9];
    float* out = (float*)d_out;

    float *q_p, *k_p, *v_p;
    __half *ah_p, *xh_p, *wt_p;
    cudaGetSymbolAddress((void**)&q_p,  g_q);
    cudaGetSymbolAddress((void**)&k_p,  g_k);
    cudaGetSymbolAddress((void**)&v_p,  g_v);
    cudaGetSymbolAddress((void**)&ah_p, g_ah);
    cudaGetSymbolAddress((void**)&xh_p, g_xh);
    cudaGetSymbolAddress((void**)&wt_p, g_wth);

    constexpr int SM128 = NS * (A_H + 128 * SAH) * 2;   // 81920
    constexpr int SM64  = NS * (A_H + 64  * SAH) * 2;   // 61440
    cudaFuncSetAttribute(gemm_h<128>, cudaFuncAttributeMaxDynamicSharedMemorySize, SM128);
    cudaFuncSetAttribute(gemm_h<64>,  cudaFuncAttributeMaxDynamicSharedMemorySize, SM64);

    const size_t WSZ = (size_t)DM * DM;
    const int nx4 = TOKENS * DM / 4;
    xcvt_kernel<<<(nx4 + 255) / 256, 256>>>(x, xh_p, nx4);
    wtrans_kernel<<<dim3(DM / 32, DM / 32, 4), 256>>>(Wq, Wk, Wv, Wo);

    dim3 gQKV(DM / 128, TOKENS / BM, 3);   // (16, 8, 3)
    gemm_h<128><<<gQKV, 256, SM128>>>(xh_p,
        wt_p, wt_p + WSZ, wt_p + 2 * WSZ,
        bq, bk, bv, q_p, k_p, v_p);

    attn_kernel<<<TOKENS, 128>>>();

    dim3 gO(DM / 64, TOKENS / BM, 1);      // (32, 8, 1) = 256 CTAs
    gemm_h<64><<<gO, 256, SM64>>>(ah_p,
        wt_p + 3 * WSZ, wt_p + 3 * WSZ, wt_p + 3 * WSZ,
        bo, bo, bo, out, out, out);
}

// round 13
// speedup vs baseline: 1.9649x; 1.2361x over previous
#include <cuda_runtime.h>
#include <cuda_fp16.h>
#include <cstdint>

// Problem constants: B=4, S=256, D_MODEL=2048, H=256, HEAD_DIM=8
#define TOKENS   1024
#define DM       2048
#define NHEADS   256

// ---------------------------------------------------------------------------
// Scratch (__device__ globals; allocation-free rule)
// ---------------------------------------------------------------------------
__device__ __align__(16) float  g_q[TOKENS * DM];
__device__ __align__(16) float  g_k[TOKENS * DM];
__device__ __align__(16) float  g_v[TOKENS * DM];
__device__ __align__(16) __half g_ah[TOKENS * DM];      // attn out (fp16)
__device__ __align__(16) __half g_xh[TOKENS * DM];      // x (fp16)
__device__ __align__(16) __half g_wth[4 * DM * DM];     // W^T fp16 (Wq,Wk,Wv,Wo), [N][K]

__device__ __forceinline__ void cp16(uint32_t saddr, const void* gptr) {
    asm volatile("cp.async.cg.shared.global [%0], [%1], 16;\n" :: "r"(saddr), "l"(gptr));
}
__device__ __forceinline__ void mma_f16(float* c, const uint32_t* a, const uint32_t* b) {
    asm volatile(
        "mma.sync.aligned.m16n8k16.row.col.f32.f16.f16.f32 "
        "{%0,%1,%2,%3}, {%4,%5,%6,%7}, {%8,%9}, {%0,%1,%2,%3};"
        : "+f"(c[0]), "+f"(c[1]), "+f"(c[2]), "+f"(c[3])
        : "r"(a[0]), "r"(a[1]), "r"(a[2]), "r"(a[3]), "r"(b[0]), "r"(b[1]));
}
__device__ __forceinline__ void ldsm4(uint32_t& r0, uint32_t& r1, uint32_t& r2, uint32_t& r3,
                                      uint32_t addr) {
    asm volatile("ldmatrix.sync.aligned.m8n8.x4.shared.b16 {%0,%1,%2,%3}, [%4];"
                 : "=r"(r0), "=r"(r1), "=r"(r2), "=r"(r3) : "r"(addr));
}
__device__ __forceinline__ void ldsm2t(uint32_t& r0, uint32_t& r1, uint32_t addr) {
    asm volatile("ldmatrix.sync.aligned.m8n8.x2.trans.shared.b16 {%0,%1}, [%2];"
                 : "=r"(r0), "=r"(r1) : "r"(addr));
}
__device__ __forceinline__ float ex2f(float x) {
    float y; asm("ex2.approx.f32 %0, %1;" : "=f"(y) : "f"(x)); return y;
}
// pack: result = {lo=b, hi=a}
__device__ __forceinline__ uint32_t cvtpk(float a, float b) {
    uint32_t r; asm("cvt.rn.f16x2.f32 %0, %1, %2;" : "=r"(r) : "f"(a), "f"(b)); return r;
}

// ---------------------------------------------------------------------------
// FP16 mma.sync GEMM (templated BN): C(f32) = A(h)[M,K] @ Wt(h)[N,K]^T + bias
// (unchanged from best-measured configuration)
// ---------------------------------------------------------------------------
#define BM 128
#define BK 32
#define NS 4
#define NK (DM / BK)              // 64
#define SAH 40                    // halves per row (80 B, LDSM conflict-free)
#define A_H (BM * SAH)            // 5120 halves

template <int BNt>
__global__ void __launch_bounds__(256, 2) gemm_h(
    const __half* __restrict__ A,
    const __half* __restrict__ T0, const __half* __restrict__ T1, const __half* __restrict__ T2,
    const float* __restrict__ b0, const float* __restrict__ b1, const float* __restrict__ b2,
    float* __restrict__ C0, float* __restrict__ C1, float* __restrict__ C2)
{
    constexpr int WCN   = BNt / 32;
    constexpr int MI    = (BNt == 128) ? 4 : 2;
    constexpr int B_H   = BNt * SAH;
    constexpr int STG_B = (A_H + B_H) * 2;
    constexpr int BCH   = BNt * 4 / 256;
    constexpr int SCt   = BNt + 4;

    extern __shared__ char smem[];
    uint32_t sbase;
    asm("{ .reg .u64 t; cvta.to.shared.u64 t, %1; cvt.u32.u64 %0, t; }" : "=r"(sbase) : "l"(smem));

    const int z = blockIdx.z;
    const __half* Wt  = (z == 0) ? T0 : (z == 1) ? T1 : T2;
    const float* bias = (z == 0) ? b0 : (z == 1) ? b1 : b2;
    float*       C    = (z == 0) ? C0 : (z == 1) ? C1 : C2;

    const int tid  = threadIdx.x;
    const int lane = tid & 31;
    const int g    = lane >> 2;
    const int t    = lane & 3;
    const int warp = tid >> 5;
    const int mrow0 = (warp / WCN) * (MI * 16);
    const int ncol0 = (warp % WCN) * 32;
    const int bm = blockIdx.y * BM;
    const int bn = blockIdx.x * BNt;

    const uint32_t a_lm = (uint32_t)((mrow0 + (lane & 15)) * SAH + (lane >> 4) * 8);
    const uint32_t b_lm = (uint32_t)((ncol0 + (lane >> 4) * 8 + (lane & 7)) * SAH
                                     + ((lane >> 3) & 1) * 8);

    float acc[MI][4][4];
#pragma unroll
    for (int i = 0; i < MI; i++)
#pragma unroll
        for (int j = 0; j < 4; j++)
#pragma unroll
            for (int e = 0; e < 4; e++) acc[i][j][e] = 0.0f;

    auto fill = [&](int it) {
        const uint32_t ab = sbase + (uint32_t)((it % NS) * STG_B);
        const uint32_t bb = ab + A_H * 2;
        const int kt = it * BK;
        const __half* Ag = A  + (size_t)bm * DM + kt;
        const __half* Bg = Wt + (size_t)bn * DM + kt;
#pragma unroll
        for (int l = 0; l < 2; l++) {
            int i = tid + l * 256;
            int r = i >> 2, c = i & 3;
            cp16(ab + (uint32_t)(r * 80 + c * 16), Ag + (size_t)r * DM + c * 8);
        }
#pragma unroll
        for (int l = 0; l < BCH; l++) {
            int i = tid + l * 256;
            int r = i >> 2, c = i & 3;
            cp16(bb + (uint32_t)(r * 80 + c * 16), Bg + (size_t)r * DM + c * 8);
        }
        asm volatile("cp.async.commit_group;" ::: "memory");
    };

    fill(0); fill(1); fill(2);

#pragma unroll 1
    for (int it = 0; it < NK; it++) {
        asm volatile("cp.async.wait_group 2;" ::: "memory");
        __syncthreads();
        if (it + 3 < NK) fill(it + 3);
        else asm volatile("cp.async.commit_group;" ::: "memory");

        const uint32_t abase = sbase + (uint32_t)((it % NS) * STG_B);
        const uint32_t bbase = abase + A_H * 2;

#pragma unroll
        for (int kk = 0; kk < BK; kk += 16) {
            uint32_t af[MI][4], bf[4][2];
#pragma unroll
            for (int mi = 0; mi < MI; mi++)
                ldsm4(af[mi][0], af[mi][1], af[mi][2], af[mi][3],
                      abase + (a_lm + (uint32_t)(mi * 16 * SAH + kk)) * 2);
#pragma unroll
            for (int p = 0; p < 2; p++)
                ldsm4(bf[2*p][0], bf[2*p][1], bf[2*p+1][0], bf[2*p+1][1],
                      bbase + (b_lm + (uint32_t)(p * 16 * SAH + kk)) * 2);
#pragma unroll
            for (int mi = 0; mi < MI; mi++)
#pragma unroll
                for (int nj = 0; nj < 4; nj++)
                    mma_f16(acc[mi][nj], af[mi], bf[nj]);
        }
    }

    __syncthreads();
    float* Cs = reinterpret_cast<float*>(smem);
#pragma unroll
    for (int mi = 0; mi < MI; mi++) {
        const int r0 = mrow0 + mi * 16 + g;
#pragma unroll
        for (int nj = 0; nj < 4; nj++) {
            const int c = ncol0 + nj * 8 + 2 * t;
            *reinterpret_cast<float2*>(&Cs[(r0)     * SCt + c]) = make_float2(acc[mi][nj][0], acc[mi][nj][1]);
            *reinterpret_cast<float2*>(&Cs[(r0 + 8) * SCt + c]) = make_float2(acc[mi][nj][2], acc[mi][nj][3]);
        }
    }
    __syncthreads();

#pragma unroll
    for (int l = 0; l < BM * BNt / 4 / 256; l++) {
        int i = tid + l * 256;
        int r = i / (BNt / 4), c = (i % (BNt / 4)) * 4;
        float4 v  = *reinterpret_cast<float4*>(&Cs[r * SCt + c]);
        float4 bb = *reinterpret_cast<const float4*>(&bias[bn + c]);
        v.x += bb.x; v.y += bb.y; v.z += bb.z; v.w += bb.w;
        *reinterpret_cast<float4*>(&C[(size_t)(bm + r) * DM + bn + c]) = v;
    }
}

// ---------------------------------------------------------------------------
// Prep: x -> half;  W[k][n] f32 -> Wt[n][k] half (transpose + convert)
// ---------------------------------------------------------------------------
__global__ void xcvt_kernel(const float* __restrict__ src, __half* __restrict__ dst, int n4)
{
    int i = blockIdx.x * blockDim.x + threadIdx.x;
    if (i < n4) {
        float4 v = reinterpret_cast<const float4*>(src)[i];
        __half2* d = reinterpret_cast<__half2*>(dst) + 2 * i;
        d[0] = __floats2half2_rn(v.x, v.y);
        d[1] = __floats2half2_rn(v.z, v.w);
    }
}

__global__ void wtrans_kernel(
    const float* __restrict__ W0, const float* __restrict__ W1,
    const float* __restrict__ W2, const float* __restrict__ W3)
{
    __shared__ float tsm[32][33];
    const int zz = blockIdx.z;
    const float* src = (zz == 0) ? W0 : (zz == 1) ? W1 : (zz == 2) ? W2 : W3;
    __half* dst = g_wth + (size_t)zz * DM * DM;

    const int n0 = blockIdx.x * 32;
    const int k0 = blockIdx.y * 32;
    const int tid = threadIdx.x;
    const int tx = tid & 31, ty = tid >> 5;

#pragma unroll
    for (int j = ty; j < 32; j += 8)
        tsm[j][tx] = src[(size_t)(k0 + j) * DM + n0 + tx];
    __syncthreads();

#pragma unroll
    for (int idx = tid; idx < 32 * 16; idx += 256) {
        int r = idx >> 4, c = idx & 15;
        __half2 h = __floats2half2_rn(tsm[2 * c][r], tsm[2 * c + 1][r]);
        *reinterpret_cast<__half2*>(&dst[(size_t)(n0 + r) * DM + k0 + 2 * c]) = h;
    }
}

// ---------------------------------------------------------------------------
// Flash-style MMA attention: 1 block = 1 token, 256 threads (8 warps x 32 q).
// S = (Q*c) K^T via m16n8k16 (d=8 zero-padded to 16), P = ex2(S) in f32,
// pack to fp16 A-frags (acc->A identity), O += P V via m16n8k16 with
// ldmatrix.trans on V.  Rowsum via intra-quad shfl; normalize at the end.
// ---------------------------------------------------------------------------
#define SQH 24      // Q/K smem stride in halves (48 B -> ldmatrix conflict-free)

__global__ void __launch_bounds__(256) attn_kernel()
{
    __shared__ __half sQ[NHEADS * SQH];    // 12 KB (cols 8..15 zeroed: mma k-pad)
    __shared__ __half sK[NHEADS * SQH];    // 12 KB (cols 8..15 zeroed)
    __shared__ __half sV[NHEADS * 8];      // 4 KB

    const int tk   = blockIdx.x;
    const int tid  = threadIdx.x;
    const int lane = tid & 31;
    const int warp = tid >> 5;
    const int qb   = warp * 32;            // warp's q-row base

    uint32_t sQb, sKb, sVb;
    asm("{ .reg .u64 t; cvta.to.shared.u64 t, %1; cvt.u32.u64 %0, t; }" : "=r"(sQb) : "l"(sQ));
    asm("{ .reg .u64 t; cvta.to.shared.u64 t, %1; cvt.u32.u64 %0, t; }" : "=r"(sKb) : "l"(sK));
    asm("{ .reg .u64 t; cvta.to.shared.u64 t, %1; cvt.u32.u64 %0, t; }" : "=r"(sVb) : "l"(sV));

    // ---- stage: thread = one head-row; scale folded into Q ----
    const float sc = 0.35355339059327373f * 1.4426950408889634f;   // log2e/sqrt(8)
    {
        const int r = tid;
        const float4* q4 = reinterpret_cast<const float4*>(&g_q[(size_t)tk * DM + r * 8]);
        const float4* k4 = reinterpret_cast<const float4*>(&g_k[(size_t)tk * DM + r * 8]);
        const float4* v4 = reinterpret_cast<const float4*>(&g_v[(size_t)tk * DM + r * 8]);
        float4 q0 = q4[0], q1 = q4[1];
        uint4 qh;
        qh.x = cvtpk(q0.y * sc, q0.x * sc);
        qh.y = cvtpk(q0.w * sc, q0.z * sc);
        qh.z = cvtpk(q1.y * sc, q1.x * sc);
        qh.w = cvtpk(q1.w * sc, q1.z * sc);
        *reinterpret_cast<uint4*>(&sQ[r * SQH])     = qh;
        *reinterpret_cast<uint4*>(&sQ[r * SQH + 8]) = make_uint4(0, 0, 0, 0);
        float4 k0 = k4[0], k1 = k4[1];
        uint4 kh;
        kh.x = cvtpk(k0.y, k0.x);
        kh.y = cvtpk(k0.w, k0.z);
        kh.z = cvtpk(k1.y, k1.x);
        kh.w = cvtpk(k1.w, k1.z);
        *reinterpret_cast<uint4*>(&sK[r * SQH])     = kh;
        *reinterpret_cast<uint4*>(&sK[r * SQH + 8]) = make_uint4(0, 0, 0, 0);
        float4 v0 = v4[0], v1 = v4[1];
        uint4 vh;
        vh.x = cvtpk(v0.y, v0.x);
        vh.y = cvtpk(v0.w, v0.z);
        vh.z = cvtpk(v1.y, v1.x);
        vh.w = cvtpk(v1.w, v1.z);
        *reinterpret_cast<uint4*>(&sV[r * 8]) = vh;
    }
    __syncthreads();

    // ---- preload Q A-frags (reused for all g-blocks) ----
    uint32_t af[2][4];
    {
        const uint32_t a_lm = (uint32_t)((qb + (lane & 15)) * SQH + (lane >> 4) * 8);
#pragma unroll
        for (int mi = 0; mi < 2; mi++)
            ldsm4(af[mi][0], af[mi][1], af[mi][2], af[mi][3],
                  sQb + (a_lm + (uint32_t)(mi * 16 * SQH)) * 2);
    }

    float oacc[2][4];
#pragma unroll
    for (int mi = 0; mi < 2; mi++)
#pragma unroll
        for (int e = 0; e < 4; e++) oacc[mi][e] = 0.0f;
    float rs[2][2] = {{0.f, 0.f}, {0.f, 0.f}};

#pragma unroll
    for (int gb = 0; gb < 4; gb++) {
        // K B-frags: 64 g (8 nj tiles) x k16
        uint32_t bf[8][2];
        const uint32_t b_lm = (uint32_t)((gb * 64 + (lane >> 4) * 8 + (lane & 7)) * SQH
                                         + ((lane >> 3) & 1) * 8);
#pragma unroll
        for (int p = 0; p < 4; p++)
            ldsm4(bf[2*p][0], bf[2*p][1], bf[2*p+1][0], bf[2*p+1][1],
                  sKb + (b_lm + (uint32_t)(p * 16 * SQH)) * 2);

        // S = Q K^T  (16 mma)
        float sacc[2][8][4];
#pragma unroll
        for (int mi = 0; mi < 2; mi++)
#pragma unroll
            for (int nj = 0; nj < 8; nj++) {
#pragma unroll
                for (int e = 0; e < 4; e++) sacc[mi][nj][e] = 0.0f;
                mma_f16(sacc[mi][nj], af[mi], bf[nj]);
            }

        // softmax transform: p = ex2(s); accumulate rowsums; pack P A-frags
        uint32_t pf[2][4][4];
#pragma unroll
        for (int mi = 0; mi < 2; mi++)
#pragma unroll
            for (int nj = 0; nj < 8; nj++) {
                float e0 = ex2f(sacc[mi][nj][0]);
                float e1 = ex2f(sacc[mi][nj][1]);
                float e2 = ex2f(sacc[mi][nj][2]);
                float e3 = ex2f(sacc[mi][nj][3]);
                rs[mi][0] += e0 + e1;
                rs[mi][1] += e2 + e3;
                const int p = nj >> 1;
                if ((nj & 1) == 0) {
                    pf[mi][p][0] = cvtpk(e1, e0);
                    pf[mi][p][1] = cvtpk(e3, e2);
                } else {
                    pf[mi][p][2] = cvtpk(e1, e0);
                    pf[mi][p][3] = cvtpk(e3, e2);
                }
            }

        // V B-frags (k=g): ldmatrix.x2.trans, rows = V[g, 0..7]
        uint32_t vf[4][2];
#pragma unroll
        for (int p = 0; p < 4; p++) {
            const uint32_t vaddr = sVb + (uint32_t)((gb * 64 + p * 16 + (lane & 15)) * 8) * 2;
            ldsm2t(vf[p][0], vf[p][1], vaddr);
        }

        // O += P V  (8 mma)
#pragma unroll
        for (int mi = 0; mi < 2; mi++)
#pragma unroll
            for (int p = 0; p < 4; p++)
                mma_f16(oacc[mi], pf[mi][p], vf[p]);
    }

    // ---- rowsum reduction across the lane quad (cols live on lanes t=0..3) ----
#pragma unroll
    for (int mi = 0; mi < 2; mi++)
#pragma unroll
        for (int j = 0; j < 2; j++) {
            rs[mi][j] += __shfl_xor_sync(0xFFFFFFFF, rs[mi][j], 1);
            rs[mi][j] += __shfl_xor_sync(0xFFFFFFFF, rs[mi][j], 2);
        }

    // ---- normalize + store (fp16, direct A-operand layout for O-GEMM) ----
#pragma unroll
    for (int mi = 0; mi < 2; mi++) {
        const int r0 = qb + mi * 16 + (lane >> 2);
        const int c  = 2 * (lane & 3);
        const float inv0 = 1.0f / rs[mi][0];
        const float inv1 = 1.0f / rs[mi][1];
        *reinterpret_cast<__half2*>(&g_ah[(size_t)tk * DM + r0 * 8 + c]) =
            __floats2half2_rn(oacc[mi][0] * inv0, oacc[mi][1] * inv0);
        *reinterpret_cast<__half2*>(&g_ah[(size_t)tk * DM + (r0 + 8) * 8 + c]) =
            __floats2half2_rn(oacc[mi][2] * inv1, oacc[mi][3] * inv1);
    }
}

// ---------------------------------------------------------------------------
// Launch
// ---------------------------------------------------------------------------
extern "C" void kernel_launch(void* const* d_in, const int* in_sizes, int n_in,
                              void* d_out, int out_size)
{
    const float* x  = (const float*)d_in[0];
    // d_in[1] = phase_shift: cos^2+sin^2 cancels analytically; unused.
    const float* Wq = (const float*)d_in[2];
    const float* bq = (const float*)d_in[3];
    const float* Wk = (const float*)d_in[4];
    const float* bk = (const float*)d_in[5];
    const float* Wv = (const float*)d_in[6];
    const float* bv = (const float*)d_in[7];
    const float* Wo = (const float*)d_in[8];
    const float* bo = (const float*)d_in[9];
    float* out = (float*)d_out;

    float *q_p, *k_p, *v_p;
    __half *ah_p, *xh_p, *wt_p;
    cudaGetSymbolAddress((void**)&q_p,  g_q);
    cudaGetSymbolAddress((void**)&k_p,  g_k);
    cudaGetSymbolAddress((void**)&v_p,  g_v);
    cudaGetSymbolAddress((void**)&ah_p, g_ah);
    cudaGetSymbolAddress((void**)&xh_p, g_xh);
    cudaGetSymbolAddress((void**)&wt_p, g_wth);

    constexpr int SM128 = NS * (A_H + 128 * SAH) * 2;   // 81920
    constexpr int SM64  = NS * (A_H + 64  * SAH) * 2;   // 61440
    cudaFuncSetAttribute(gemm_h<128>, cudaFuncAttributeMaxDynamicSharedMemorySize, SM128);
    cudaFuncSetAttribute(gemm_h<64>,  cudaFuncAttributeMaxDynamicSharedMemorySize, SM64);

    const size_t WSZ = (size_t)DM * DM;
    const int nx4 = TOKENS * DM / 4;
    xcvt_kernel<<<(nx4 + 255) / 256, 256>>>(x, xh_p, nx4);
    wtrans_kernel<<<dim3(DM / 32, DM / 32, 4), 256>>>(Wq, Wk, Wv, Wo);

    dim3 gQKV(DM / 128, TOKENS / BM, 3);   // (16, 8, 3)
    gemm_h<128><<<gQKV, 256, SM128>>>(xh_p,
        wt_p, wt_p + WSZ, wt_p + 2 * WSZ,
        bq, bk, bv, q_p, k_p, v_p);

    attn_kernel<<<TOKENS, 256>>>();

    dim3 gO(DM / 64, TOKENS / BM, 1);      // (32, 8, 1) = 256 CTAs
    gemm_h<64><<<gO, 256, SM64>>>(ah_p,
        wt_p + 3 * WSZ, wt_p + 3 * WSZ, wt_p + 3 * WSZ,
        bo, bo, bo, out, out, out);
}

// round 14
// speedup vs baseline: 2.0748x; 1.0559x over previous
#include <cuda_runtime.h>
#include <cuda_fp16.h>
#include <cstdint>

// Problem constants: B=4, S=256, D_MODEL=2048, H=256, HEAD_DIM=8
#define TOKENS   1024
#define DM       2048
#define NHEADS   256

// softmax scale with ex2 folding: log2(e)/sqrt(8)
#define SC_Q 0.510072818751329f

// ---------------------------------------------------------------------------
// Scratch (__device__ globals; allocation-free rule)
// ---------------------------------------------------------------------------
__device__ __align__(16) __half g_qh[TOKENS * DM];      // Q (fp16, pre-scaled by SC_Q)
__device__ __align__(16) __half g_kh[TOKENS * DM];      // K (fp16)
__device__ __align__(16) __half g_vh[TOKENS * DM];      // V (fp16)
__device__ __align__(16) __half g_ah[TOKENS * DM];      // attn out (fp16)
__device__ __align__(16) __half g_xh[TOKENS * DM];      // x (fp16)
__device__ __align__(16) __half g_wth[4 * DM * DM];     // W^T fp16 (Wq,Wk,Wv,Wo), [N][K]

__device__ __forceinline__ void cp16(uint32_t saddr, const void* gptr) {
    asm volatile("cp.async.cg.shared.global [%0], [%1], 16;\n" :: "r"(saddr), "l"(gptr));
}
__device__ __forceinline__ void mma_f16(float* c, const uint32_t* a, const uint32_t* b) {
    asm volatile(
        "mma.sync.aligned.m16n8k16.row.col.f32.f16.f16.f32 "
        "{%0,%1,%2,%3}, {%4,%5,%6,%7}, {%8,%9}, {%0,%1,%2,%3};"
        : "+f"(c[0]), "+f"(c[1]), "+f"(c[2]), "+f"(c[3])
        : "r"(a[0]), "r"(a[1]), "r"(a[2]), "r"(a[3]), "r"(b[0]), "r"(b[1]));
}
__device__ __forceinline__ void ldsm4(uint32_t& r0, uint32_t& r1, uint32_t& r2, uint32_t& r3,
                                      uint32_t addr) {
    asm volatile("ldmatrix.sync.aligned.m8n8.x4.shared.b16 {%0,%1,%2,%3}, [%4];"
                 : "=r"(r0), "=r"(r1), "=r"(r2), "=r"(r3) : "r"(addr));
}
__device__ __forceinline__ void ldsm2t(uint32_t& r0, uint32_t& r1, uint32_t addr) {
    asm volatile("ldmatrix.sync.aligned.m8n8.x2.trans.shared.b16 {%0,%1}, [%2];"
                 : "=r"(r0), "=r"(r1) : "r"(addr));
}
__device__ __forceinline__ float ex2f(float x) {
    float y; asm("ex2.approx.f32 %0, %1;" : "=f"(y) : "f"(x)); return y;
}
// pack: result = {lo=b, hi=a}
__device__ __forceinline__ uint32_t cvtpk(float a, float b) {
    uint32_t r; asm("cvt.rn.f16x2.f32 %0, %1, %2;" : "=r"(r) : "f"(a), "f"(b)); return r;
}

// ---------------------------------------------------------------------------
// FP16 mma.sync GEMM (templated BN, output type):
//   C = (A(h)[M,K] @ Wt(h)[N,K]^T + bias) * zscale
// BM=128, BK=32, 4-stage cp.async ring, ldmatrix fragment loads.
// HOUT: write __half (QKV path; zscale=SC_Q for z==0).  Else f32 (O path).
// ---------------------------------------------------------------------------
#define BM 128
#define BK 32
#define NS 4
#define NK (DM / BK)              // 64
#define SAH 40                    // halves per row (80 B, LDSM conflict-free)
#define A_H (BM * SAH)            // 5120 halves

template <int BNt, bool HOUT>
__global__ void __launch_bounds__(256, 2) gemm_h(
    const __half* __restrict__ A,
    const __half* __restrict__ T0, const __half* __restrict__ T1, const __half* __restrict__ T2,
    const float* __restrict__ b0, const float* __restrict__ b1, const float* __restrict__ b2,
    void* __restrict__ C0, void* __restrict__ C1, void* __restrict__ C2)
{
    constexpr int WCN   = BNt / 32;
    constexpr int MI    = (BNt == 128) ? 4 : 2;
    constexpr int B_H   = BNt * SAH;
    constexpr int STG_B = (A_H + B_H) * 2;
    constexpr int BCH   = BNt * 4 / 256;
    constexpr int SCt   = BNt + 4;

    extern __shared__ char smem[];
    uint32_t sbase;
    asm("{ .reg .u64 t; cvta.to.shared.u64 t, %1; cvt.u32.u64 %0, t; }" : "=r"(sbase) : "l"(smem));

    const int z = blockIdx.z;
    const __half* Wt  = (z == 0) ? T0 : (z == 1) ? T1 : T2;
    const float* bias = (z == 0) ? b0 : (z == 1) ? b1 : b2;
    void*        C    = (z == 0) ? C0 : (z == 1) ? C1 : C2;
    const float zs    = (HOUT && z == 0) ? SC_Q : 1.0f;

    const int tid  = threadIdx.x;
    const int lane = tid & 31;
    const int g    = lane >> 2;
    const int t    = lane & 3;
    const int warp = tid >> 5;
    const int mrow0 = (warp / WCN) * (MI * 16);
    const int ncol0 = (warp % WCN) * 32;
    const int bm = blockIdx.y * BM;
    const int bn = blockIdx.x * BNt;

    const uint32_t a_lm = (uint32_t)((mrow0 + (lane & 15)) * SAH + (lane >> 4) * 8);
    const uint32_t b_lm = (uint32_t)((ncol0 + (lane >> 4) * 8 + (lane & 7)) * SAH
                                     + ((lane >> 3) & 1) * 8);

    float acc[MI][4][4];
#pragma unroll
    for (int i = 0; i < MI; i++)
#pragma unroll
        for (int j = 0; j < 4; j++)
#pragma unroll
            for (int e = 0; e < 4; e++) acc[i][j][e] = 0.0f;

    auto fill = [&](int it) {
        const uint32_t ab = sbase + (uint32_t)((it % NS) * STG_B);
        const uint32_t bb = ab + A_H * 2;
        const int kt = it * BK;
        const __half* Ag = A  + (size_t)bm * DM + kt;
        const __half* Bg = Wt + (size_t)bn * DM + kt;
#pragma unroll
        for (int l = 0; l < 2; l++) {
            int i = tid + l * 256;
            int r = i >> 2, c = i & 3;
            cp16(ab + (uint32_t)(r * 80 + c * 16), Ag + (size_t)r * DM + c * 8);
        }
#pragma unroll
        for (int l = 0; l < BCH; l++) {
            int i = tid + l * 256;
            int r = i >> 2, c = i & 3;
            cp16(bb + (uint32_t)(r * 80 + c * 16), Bg + (size_t)r * DM + c * 8);
        }
        asm volatile("cp.async.commit_group;" ::: "memory");
    };

    fill(0); fill(1); fill(2);

#pragma unroll 1
    for (int it = 0; it < NK; it++) {
        asm volatile("cp.async.wait_group 2;" ::: "memory");
        __syncthreads();
        if (it + 3 < NK) fill(it + 3);
        else asm volatile("cp.async.commit_group;" ::: "memory");

        const uint32_t abase = sbase + (uint32_t)((it % NS) * STG_B);
        const uint32_t bbase = abase + A_H * 2;

#pragma unroll
        for (int kk = 0; kk < BK; kk += 16) {
            uint32_t af[MI][4], bf[4][2];
#pragma unroll
            for (int mi = 0; mi < MI; mi++)
                ldsm4(af[mi][0], af[mi][1], af[mi][2], af[mi][3],
                      abase + (a_lm + (uint32_t)(mi * 16 * SAH + kk)) * 2);
#pragma unroll
            for (int p = 0; p < 2; p++)
                ldsm4(bf[2*p][0], bf[2*p][1], bf[2*p+1][0], bf[2*p+1][1],
                      bbase + (b_lm + (uint32_t)(p * 16 * SAH + kk)) * 2);
#pragma unroll
            for (int mi = 0; mi < MI; mi++)
#pragma unroll
                for (int nj = 0; nj < 4; nj++)
                    mma_f16(acc[mi][nj], af[mi], bf[nj]);
        }
    }

    // ---- epilogue: stage acc to smem, fused bias(+scale), coalesced stores ----
    __syncthreads();
    float* Cs = reinterpret_cast<float*>(smem);
#pragma unroll
    for (int mi = 0; mi < MI; mi++) {
        const int r0 = mrow0 + mi * 16 + g;
#pragma unroll
        for (int nj = 0; nj < 4; nj++) {
            const int c = ncol0 + nj * 8 + 2 * t;
            *reinterpret_cast<float2*>(&Cs[(r0)     * SCt + c]) = make_float2(acc[mi][nj][0], acc[mi][nj][1]);
            *reinterpret_cast<float2*>(&Cs[(r0 + 8) * SCt + c]) = make_float2(acc[mi][nj][2], acc[mi][nj][3]);
        }
    }
    __syncthreads();

#pragma unroll
    for (int l = 0; l < BM * BNt / 4 / 256; l++) {
        int i = tid + l * 256;
        int r = i / (BNt / 4), c = (i % (BNt / 4)) * 4;
        float4 v  = *reinterpret_cast<float4*>(&Cs[r * SCt + c]);
        float4 bb = *reinterpret_cast<const float4*>(&bias[bn + c]);
        v.x = (v.x + bb.x) * zs; v.y = (v.y + bb.y) * zs;
        v.z = (v.z + bb.z) * zs; v.w = (v.w + bb.w) * zs;
        if (HOUT) {
            uint2 h;
            h.x = cvtpk(v.y, v.x);
            h.y = cvtpk(v.w, v.z);
            *reinterpret_cast<uint2*>(
                reinterpret_cast<__half*>(C) + (size_t)(bm + r) * DM + bn + c) = h;
        } else {
            *reinterpret_cast<float4*>(
                reinterpret_cast<float*>(C) + (size_t)(bm + r) * DM + bn + c) = v;
        }
    }
}

// ---------------------------------------------------------------------------
// Prep: x -> half;  W[k][n] f32 -> Wt[n][k] half (64x64 tiles, coalesced)
// ---------------------------------------------------------------------------
__global__ void xcvt_kernel(const float* __restrict__ src, __half* __restrict__ dst, int n4)
{
    int i = blockIdx.x * blockDim.x + threadIdx.x;
    if (i < n4) {
        float4 v = reinterpret_cast<const float4*>(src)[i];
        __half2* d = reinterpret_cast<__half2*>(dst) + 2 * i;
        d[0] = __floats2half2_rn(v.x, v.y);
        d[1] = __floats2half2_rn(v.z, v.w);
    }
}

__global__ void wtrans_kernel(
    const float* __restrict__ W0, const float* __restrict__ W1,
    const float* __restrict__ W2, const float* __restrict__ W3)
{
    __shared__ float tsm[64][65];
    const int zz = blockIdx.z;
    const float* src = (zz == 0) ? W0 : (zz == 1) ? W1 : (zz == 2) ? W2 : W3;
    __half* dst = g_wth + (size_t)zz * DM * DM;

    const int n0 = blockIdx.x * 64;
    const int k0 = blockIdx.y * 64;
    const int tid = threadIdx.x;           // 256
    const int rx = tid >> 6, cx = tid & 63;

#pragma unroll
    for (int j = 0; j < 16; j++) {         // load 64 k-rows x 64 n
        int row = j * 4 + rx;
        tsm[row][cx] = src[(size_t)(k0 + row) * DM + n0 + cx];
    }
    __syncthreads();

#pragma unroll
    for (int j = 0; j < 8; j++) {          // store 64 n-rows x 32 half2 (128B rows)
        int idx = tid + j * 256;
        int r = idx >> 5, c = idx & 31;
        __half2 h = __floats2half2_rn(tsm[2 * c][r], tsm[2 * c + 1][r]);
        *reinterpret_cast<__half2*>(&dst[(size_t)(n0 + r) * DM + k0 + 2 * c]) = h;
    }
}

// ---------------------------------------------------------------------------
// Flash-style MMA attention (fp16 inputs; Q pre-scaled in GEMM epilogue).
// 1 block = 1 token, 256 threads (8 warps x 32 q).
// ---------------------------------------------------------------------------
#define SQH 24      // Q/K smem stride in halves (48 B -> ldmatrix conflict-free)

__global__ void __launch_bounds__(256) attn_kernel()
{
    __shared__ __half sQ[NHEADS * SQH];    // cols 8..15 zeroed (mma k-pad)
    __shared__ __half sK[NHEADS * SQH];
    __shared__ __half sV[NHEADS * 8];

    const int tk   = blockIdx.x;
    const int tid  = threadIdx.x;
    const int lane = tid & 31;
    const int warp = tid >> 5;
    const int qb   = warp * 32;

    uint32_t sQb, sKb, sVb;
    asm("{ .reg .u64 t; cvta.to.shared.u64 t, %1; cvt.u32.u64 %0, t; }" : "=r"(sQb) : "l"(sQ));
    asm("{ .reg .u64 t; cvta.to.shared.u64 t, %1; cvt.u32.u64 %0, t; }" : "=r"(sKb) : "l"(sK));
    asm("{ .reg .u64 t; cvta.to.shared.u64 t, %1; cvt.u32.u64 %0, t; }" : "=r"(sVb) : "l"(sV));

    // ---- stage: thread = one head-row (fp16 direct copies) ----
    {
        const int r = tid;
        const uint4 qh = *reinterpret_cast<const uint4*>(&g_qh[(size_t)tk * DM + r * 8]);
        const uint4 kh = *reinterpret_cast<const uint4*>(&g_kh[(size_t)tk * DM + r * 8]);
        const uint4 vh = *reinterpret_cast<const uint4*>(&g_vh[(size_t)tk * DM + r * 8]);
        *reinterpret_cast<uint4*>(&sQ[r * SQH])     = qh;
        *reinterpret_cast<uint4*>(&sQ[r * SQH + 8]) = make_uint4(0, 0, 0, 0);
        *reinterpret_cast<uint4*>(&sK[r * SQH])     = kh;
        *reinterpret_cast<uint4*>(&sK[r * SQH + 8]) = make_uint4(0, 0, 0, 0);
        *reinterpret_cast<uint4*>(&sV[r * 8])       = vh;
    }
    __syncthreads();

    // ---- preload Q A-frags ----
    uint32_t af[2][4];
    {
        const uint32_t a_lm = (uint32_t)((qb + (lane & 15)) * SQH + (lane >> 4) * 8);
#pragma unroll
        for (int mi = 0; mi < 2; mi++)
            ldsm4(af[mi][0], af[mi][1], af[mi][2], af[mi][3],
                  sQb + (a_lm + (uint32_t)(mi * 16 * SQH)) * 2);
    }

    float oacc[2][4];
#pragma unroll
    for (int mi = 0; mi < 2; mi++)
#pragma unroll
        for (int e = 0; e < 4; e++) oacc[mi][e] = 0.0f;
    float rs[2][2] = {{0.f, 0.f}, {0.f, 0.f}};

#pragma unroll
    for (int gb = 0; gb < 4; gb++) {
        uint32_t bf[8][2];
        const uint32_t b_lm = (uint32_t)((gb * 64 + (lane >> 4) * 8 + (lane & 7)) * SQH
                                         + ((lane >> 3) & 1) * 8);
#pragma unroll
        for (int p = 0; p < 4; p++)
            ldsm4(bf[2*p][0], bf[2*p][1], bf[2*p+1][0], bf[2*p+1][1],
                  sKb + (b_lm + (uint32_t)(p * 16 * SQH)) * 2);

        float sacc[2][8][4];
#pragma unroll
        for (int mi = 0; mi < 2; mi++)
#pragma unroll
            for (int nj = 0; nj < 8; nj++) {
#pragma unroll
                for (int e = 0; e < 4; e++) sacc[mi][nj][e] = 0.0f;
                mma_f16(sacc[mi][nj], af[mi], bf[nj]);
            }

        uint32_t pf[2][4][4];
#pragma unroll
        for (int mi = 0; mi < 2; mi++)
#pragma unroll
            for (int nj = 0; nj < 8; nj++) {
                float e0 = ex2f(sacc[mi][nj][0]);
                float e1 = ex2f(sacc[mi][nj][1]);
                float e2 = ex2f(sacc[mi][nj][2]);
                float e3 = ex2f(sacc[mi][nj][3]);
                rs[mi][0] += e0 + e1;
                rs[mi][1] += e2 + e3;
                const int p = nj >> 1;
                if ((nj & 1) == 0) {
                    pf[mi][p][0] = cvtpk(e1, e0);
                    pf[mi][p][1] = cvtpk(e3, e2);
                } else {
                    pf[mi][p][2] = cvtpk(e1, e0);
                    pf[mi][p][3] = cvtpk(e3, e2);
                }
            }

        uint32_t vf[4][2];
#pragma unroll
        for (int p = 0; p < 4; p++) {
            const uint32_t vaddr = sVb + (uint32_t)((gb * 64 + p * 16 + (lane & 15)) * 8) * 2;
            ldsm2t(vf[p][0], vf[p][1], vaddr);
        }

#pragma unroll
        for (int mi = 0; mi < 2; mi++)
#pragma unroll
            for (int p = 0; p < 4; p++)
                mma_f16(oacc[mi], pf[mi][p], vf[p]);
    }

#pragma unroll
    for (int mi = 0; mi < 2; mi++)
#pragma unroll
        for (int j = 0; j < 2; j++) {
            rs[mi][j] += __shfl_xor_sync(0xFFFFFFFF, rs[mi][j], 1);
            rs[mi][j] += __shfl_xor_sync(0xFFFFFFFF, rs[mi][j], 2);
        }

#pragma unroll
    for (int mi = 0; mi < 2; mi++) {
        const int r0 = qb + mi * 16 + (lane >> 2);
        const int c  = 2 * (lane & 3);
        const float inv0 = 1.0f / rs[mi][0];
        const float inv1 = 1.0f / rs[mi][1];
        *reinterpret_cast<__half2*>(&g_ah[(size_t)tk * DM + r0 * 8 + c]) =
            __floats2half2_rn(oacc[mi][0] * inv0, oacc[mi][1] * inv0);
        *reinterpret_cast<__half2*>(&g_ah[(size_t)tk * DM + (r0 + 8) * 8 + c]) =
            __floats2half2_rn(oacc[mi][2] * inv1, oacc[mi][3] * inv1);
    }
}

// ---------------------------------------------------------------------------
// Launch
// ---------------------------------------------------------------------------
extern "C" void kernel_launch(void* const* d_in, const int* in_sizes, int n_in,
                              void* d_out, int out_size)
{
    const float* x  = (const float*)d_in[0];
    // d_in[1] = phase_shift: cos^2+sin^2 cancels analytically; unused.
    const float* Wq = (const float*)d_in[2];
    const float* bq = (const float*)d_in[3];
    const float* Wk = (const float*)d_in[4];
    const float* bk = (const float*)d_in[5];
    const float* Wv = (const float*)d_in[6];
    const float* bv = (const float*)d_in[7];
    const float* Wo = (const float*)d_in[8];
    const float* bo = (const float*)d_in[9];
    float* out = (float*)d_out;

    __half *qh_p, *kh_p, *vh_p, *ah_p, *xh_p, *wt_p;
    cudaGetSymbolAddress((void**)&qh_p, g_qh);
    cudaGetSymbolAddress((void**)&kh_p, g_kh);
    cudaGetSymbolAddress((void**)&vh_p, g_vh);
    cudaGetSymbolAddress((void**)&ah_p, g_ah);
    cudaGetSymbolAddress((void**)&xh_p, g_xh);
    cudaGetSymbolAddress((void**)&wt_p, g_wth);

    constexpr int SM128 = NS * (A_H + 128 * SAH) * 2;   // 81920
    constexpr int SM64  = NS * (A_H + 64  * SAH) * 2;   // 61440
    cudaFuncSetAttribute((const void*)gemm_h<128, true>,
                         cudaFuncAttributeMaxDynamicSharedMemorySize, SM128);
    cudaFuncSetAttribute((const void*)gemm_h<64, false>,
                         cudaFuncAttributeMaxDynamicSharedMemorySize, SM64);

    const size_t WSZ = (size_t)DM * DM;
    const int nx4 = TOKENS * DM / 4;
    xcvt_kernel<<<(nx4 + 255) / 256, 256>>>(x, xh_p, nx4);
    wtrans_kernel<<<dim3(DM / 64, DM / 64, 4), 256>>>(Wq, Wk, Wv, Wo);

    dim3 gQKV(DM / 128, TOKENS / BM, 3);   // (16, 8, 3)
    gemm_h<128, true><<<gQKV, 256, SM128>>>(xh_p,
        wt_p, wt_p + WSZ, wt_p + 2 * WSZ,
        bq, bk, bv, qh_p, kh_p, vh_p);

    attn_kernel<<<TOKENS, 256>>>();

    dim3 gO(DM / 64, TOKENS / BM, 1);      // (32, 8, 1) = 256 CTAs
    gemm_h<64, false><<<gO, 256, SM64>>>(ah_p,
        wt_p + 3 * WSZ, wt_p + 3 * WSZ, wt_p + 3 * WSZ,
        bo, bo, bo, out, out, out);
}

// round 15
// speedup vs baseline: 2.3107x; 1.1137x over previous
#include <cuda_runtime.h>
#include <cuda_fp16.h>
#include <cstdint>

// Problem constants: B=4, S=256, D_MODEL=2048, H=256, HEAD_DIM=8
#define TOKENS   1024
#define DM       2048
#define NHEADS   256

// softmax scale with ex2 folding: log2(e)/sqrt(8)
#define SC_Q 0.510072818751329f

// ---------------------------------------------------------------------------
// Scratch (__device__ globals; allocation-free rule)
// ---------------------------------------------------------------------------
__device__ __align__(16) __half g_qh[TOKENS * DM];      // Q (fp16, pre-scaled by SC_Q)
__device__ __align__(16) __half g_kh[TOKENS * DM];      // K (fp16)
__device__ __align__(16) __half g_vh[TOKENS * DM];      // V (fp16)
__device__ __align__(16) __half g_ah[TOKENS * DM];      // attn out (fp16)
__device__ __align__(16) __half g_xh[TOKENS * DM];      // x (fp16)
__device__ __align__(16) __half g_wth[4 * DM * DM];     // W^T fp16 (Wq,Wk,Wv,Wo), [N][K]

__device__ __forceinline__ void cp16(uint32_t saddr, const void* gptr) {
    asm volatile("cp.async.cg.shared.global [%0], [%1], 16;\n" :: "r"(saddr), "l"(gptr));
}
__device__ __forceinline__ void mma_f16(float* c, const uint32_t* a, const uint32_t* b) {
    asm volatile(
        "mma.sync.aligned.m16n8k16.row.col.f32.f16.f16.f32 "
        "{%0,%1,%2,%3}, {%4,%5,%6,%7}, {%8,%9}, {%0,%1,%2,%3};"
        : "+f"(c[0]), "+f"(c[1]), "+f"(c[2]), "+f"(c[3])
        : "r"(a[0]), "r"(a[1]), "r"(a[2]), "r"(a[3]), "r"(b[0]), "r"(b[1]));
}
__device__ __forceinline__ void ldsm4(uint32_t& r0, uint32_t& r1, uint32_t& r2, uint32_t& r3,
                                      uint32_t addr) {
    asm volatile("ldmatrix.sync.aligned.m8n8.x4.shared.b16 {%0,%1,%2,%3}, [%4];"
                 : "=r"(r0), "=r"(r1), "=r"(r2), "=r"(r3) : "r"(addr));
}
__device__ __forceinline__ void ldsm2t(uint32_t& r0, uint32_t& r1, uint32_t addr) {
    asm volatile("ldmatrix.sync.aligned.m8n8.x2.trans.shared.b16 {%0,%1}, [%2];"
                 : "=r"(r0), "=r"(r1) : "r"(addr));
}
__device__ __forceinline__ float ex2f(float x) {
    float y; asm("ex2.approx.f32 %0, %1;" : "=f"(y) : "f"(x)); return y;
}
// pack: result = {lo=b, hi=a}
__device__ __forceinline__ uint32_t cvtpk(float a, float b) {
    uint32_t r; asm("cvt.rn.f16x2.f32 %0, %1, %2;" : "=r"(r) : "f"(a), "f"(b)); return r;
}

// ---------------------------------------------------------------------------
// FP16 mma.sync GEMM (templated BN, output type):
//   C = (A(h)[M,K] @ Wt(h)[N,K]^T + bias) * zscale
// BM=128, BK=64 (32 iters, halved barrier count), NS=3 cp.async ring,
// ldmatrix fragment loads, SAH=72 halves/row (144B: 4r%32 bank pattern,
// conflict-free).  HOUT: fp16 out (QKV; zscale=SC_Q for z==0) else f32 (O).
// ---------------------------------------------------------------------------
#define BM 128
#define BK 64
#define NS 3
#define NK (DM / BK)              // 32
#define SAH 72                    // halves per row (144 B)
#define A_H (BM * SAH)            // 9216 halves

template <int BNt, bool HOUT>
__global__ void __launch_bounds__(256, 2) gemm_h(
    const __half* __restrict__ A,
    const __half* __restrict__ T0, const __half* __restrict__ T1, const __half* __restrict__ T2,
    const float* __restrict__ b0, const float* __restrict__ b1, const float* __restrict__ b2,
    void* __restrict__ C0, void* __restrict__ C1, void* __restrict__ C2)
{
    constexpr int WCN   = BNt / 32;
    constexpr int MI    = (BNt == 128) ? 4 : 2;
    constexpr int B_H   = BNt * SAH;
    constexpr int STG_B = (A_H + B_H) * 2;
    constexpr int BCH   = BNt * 8 / 256;     // B 16B-chunks per thread (4 or 2)
    constexpr int SCt   = BNt + 4;

    extern __shared__ char smem[];
    uint32_t sbase;
    asm("{ .reg .u64 t; cvta.to.shared.u64 t, %1; cvt.u32.u64 %0, t; }" : "=r"(sbase) : "l"(smem));

    const int z = blockIdx.z;
    const __half* Wt  = (z == 0) ? T0 : (z == 1) ? T1 : T2;
    const float* bias = (z == 0) ? b0 : (z == 1) ? b1 : b2;
    void*        C    = (z == 0) ? C0 : (z == 1) ? C1 : C2;
    const float zs    = (HOUT && z == 0) ? SC_Q : 1.0f;

    const int tid  = threadIdx.x;
    const int lane = tid & 31;
    const int g    = lane >> 2;
    const int t    = lane & 3;
    const int warp = tid >> 5;
    const int mrow0 = (warp / WCN) * (MI * 16);
    const int ncol0 = (warp % WCN) * 32;
    const int bm = blockIdx.y * BM;
    const int bn = blockIdx.x * BNt;

    const uint32_t a_lm = (uint32_t)((mrow0 + (lane & 15)) * SAH + (lane >> 4) * 8);
    const uint32_t b_lm = (uint32_t)((ncol0 + (lane >> 4) * 8 + (lane & 7)) * SAH
                                     + ((lane >> 3) & 1) * 8);

    float acc[MI][4][4];
#pragma unroll
    for (int i = 0; i < MI; i++)
#pragma unroll
        for (int j = 0; j < 4; j++)
#pragma unroll
            for (int e = 0; e < 4; e++) acc[i][j][e] = 0.0f;

    auto fill = [&](int it) {
        const uint32_t ab = sbase + (uint32_t)((it % NS) * STG_B);
        const uint32_t bb = ab + A_H * 2;
        const int kt = it * BK;
        const __half* Ag = A  + (size_t)bm * DM + kt;
        const __half* Bg = Wt + (size_t)bn * DM + kt;
#pragma unroll
        for (int l = 0; l < 4; l++) {            // A: 128 rows x 8 chunks(16B)
            int i = tid + l * 256;
            int r = i >> 3, c = i & 7;
            cp16(ab + (uint32_t)(r * 144 + c * 16), Ag + (size_t)r * DM + c * 8);
        }
#pragma unroll
        for (int l = 0; l < BCH; l++) {          // B: BNt rows x 8 chunks
            int i = tid + l * 256;
            int r = i >> 3, c = i & 7;
            cp16(bb + (uint32_t)(r * 144 + c * 16), Bg + (size_t)r * DM + c * 8);
        }
        asm volatile("cp.async.commit_group;" ::: "memory");
    };

    fill(0); fill(1);

#pragma unroll 1
    for (int it = 0; it < NK; it++) {
        asm volatile("cp.async.wait_group 1;" ::: "memory");
        __syncthreads();
        if (it + 2 < NK) fill(it + 2);           // slot (it+2)%3 == (it-1)%3: done
        else asm volatile("cp.async.commit_group;" ::: "memory");   // keep counts

        const uint32_t abase = sbase + (uint32_t)((it % NS) * STG_B);
        const uint32_t bbase = abase + A_H * 2;

#pragma unroll
        for (int kk = 0; kk < BK; kk += 16) {
            uint32_t af[MI][4], bf[4][2];
#pragma unroll
            for (int mi = 0; mi < MI; mi++)
                ldsm4(af[mi][0], af[mi][1], af[mi][2], af[mi][3],
                      abase + (a_lm + (uint32_t)(mi * 16 * SAH + kk)) * 2);
#pragma unroll
            for (int p = 0; p < 2; p++)
                ldsm4(bf[2*p][0], bf[2*p][1], bf[2*p+1][0], bf[2*p+1][1],
                      bbase + (b_lm + (uint32_t)(p * 16 * SAH + kk)) * 2);
#pragma unroll
            for (int mi = 0; mi < MI; mi++)
#pragma unroll
                for (int nj = 0; nj < 4; nj++)
                    mma_f16(acc[mi][nj], af[mi], bf[nj]);
        }
    }

    // ---- epilogue: stage acc to smem, fused bias(+scale), coalesced stores ----
    __syncthreads();
    float* Cs = reinterpret_cast<float*>(smem);
#pragma unroll
    for (int mi = 0; mi < MI; mi++) {
        const int r0 = mrow0 + mi * 16 + g;
#pragma unroll
        for (int nj = 0; nj < 4; nj++) {
            const int c = ncol0 + nj * 8 + 2 * t;
            *reinterpret_cast<float2*>(&Cs[(r0)     * SCt + c]) = make_float2(acc[mi][nj][0], acc[mi][nj][1]);
            *reinterpret_cast<float2*>(&Cs[(r0 + 8) * SCt + c]) = make_float2(acc[mi][nj][2], acc[mi][nj][3]);
        }
    }
    __syncthreads();

#pragma unroll
    for (int l = 0; l < BM * BNt / 4 / 256; l++) {
        int i = tid + l * 256;
        int r = i / (BNt / 4), c = (i % (BNt / 4)) * 4;
        float4 v  = *reinterpret_cast<float4*>(&Cs[r * SCt + c]);
        float4 bb = *reinterpret_cast<const float4*>(&bias[bn + c]);
        v.x = (v.x + bb.x) * zs; v.y = (v.y + bb.y) * zs;
        v.z = (v.z + bb.z) * zs; v.w = (v.w + bb.w) * zs;
        if (HOUT) {
            uint2 h;
            h.x = cvtpk(v.y, v.x);
            h.y = cvtpk(v.w, v.z);
            *reinterpret_cast<uint2*>(
                reinterpret_cast<__half*>(C) + (size_t)(bm + r) * DM + bn + c) = h;
        } else {
            *reinterpret_cast<float4*>(
                reinterpret_cast<float*>(C) + (size_t)(bm + r) * DM + bn + c) = v;
        }
    }
}

// ---------------------------------------------------------------------------
// Prep: x -> half;  W[k][n] f32 -> Wt[n][k] half (64x64 tiles, coalesced)
// ---------------------------------------------------------------------------
__global__ void xcvt_kernel(const float* __restrict__ src, __half* __restrict__ dst, int n4)
{
    int i = blockIdx.x * blockDim.x + threadIdx.x;
    if (i < n4) {
        float4 v = reinterpret_cast<const float4*>(src)[i];
        __half2* d = reinterpret_cast<__half2*>(dst) + 2 * i;
        d[0] = __floats2half2_rn(v.x, v.y);
        d[1] = __floats2half2_rn(v.z, v.w);
    }
}

__global__ void wtrans_kernel(
    const float* __restrict__ W0, const float* __restrict__ W1,
    const float* __restrict__ W2, const float* __restrict__ W3)
{
    __shared__ float tsm[64][65];
    const int zz = blockIdx.z;
    const float* src = (zz == 0) ? W0 : (zz == 1) ? W1 : (zz == 2) ? W2 : W3;
    __half* dst = g_wth + (size_t)zz * DM * DM;

    const int n0 = blockIdx.x * 64;
    const int k0 = blockIdx.y * 64;
    const int tid = threadIdx.x;           // 256
    const int rx = tid >> 6, cx = tid & 63;

#pragma unroll
    for (int j = 0; j < 16; j++) {
        int row = j * 4 + rx;
        tsm[row][cx] = src[(size_t)(k0 + row) * DM + n0 + cx];
    }
    __syncthreads();

#pragma unroll
    for (int j = 0; j < 8; j++) {
        int idx = tid + j * 256;
        int r = idx >> 5, c = idx & 31;
        __half2 h = __floats2half2_rn(tsm[2 * c][r], tsm[2 * c + 1][r]);
        *reinterpret_cast<__half2*>(&dst[(size_t)(n0 + r) * DM + k0 + 2 * c]) = h;
    }
}

// ---------------------------------------------------------------------------
// Flash-style MMA attention (fp16 inputs; Q pre-scaled in GEMM epilogue).
// 1 block = 1 token, 256 threads (8 warps x 32 q).
// ---------------------------------------------------------------------------
#define SQH 24      // Q/K smem stride in halves (48 B -> ldmatrix conflict-free)

__global__ void __launch_bounds__(256) attn_kernel()
{
    __shared__ __half sQ[NHEADS * SQH];    // cols 8..15 zeroed (mma k-pad)
    __shared__ __half sK[NHEADS * SQH];
    __shared__ __half sV[NHEADS * 8];

    const int tk   = blockIdx.x;
    const int tid  = threadIdx.x;
    const int lane = tid & 31;
    const int warp = tid >> 5;
    const int qb   = warp * 32;

    uint32_t sQb, sKb, sVb;
    asm("{ .reg .u64 t; cvta.to.shared.u64 t, %1; cvt.u32.u64 %0, t; }" : "=r"(sQb) : "l"(sQ));
    asm("{ .reg .u64 t; cvta.to.shared.u64 t, %1; cvt.u32.u64 %0, t; }" : "=r"(sKb) : "l"(sK));
    asm("{ .reg .u64 t; cvta.to.shared.u64 t, %1; cvt.u32.u64 %0, t; }" : "=r"(sVb) : "l"(sV));

    // ---- stage: thread = one head-row (fp16 direct copies) ----
    {
        const int r = tid;
        const uint4 qh = *reinterpret_cast<const uint4*>(&g_qh[(size_t)tk * DM + r * 8]);
        const uint4 kh = *reinterpret_cast<const uint4*>(&g_kh[(size_t)tk * DM + r * 8]);
        const uint4 vh = *reinterpret_cast<const uint4*>(&g_vh[(size_t)tk * DM + r * 8]);
        *reinterpret_cast<uint4*>(&sQ[r * SQH])     = qh;
        *reinterpret_cast<uint4*>(&sQ[r * SQH + 8]) = make_uint4(0, 0, 0, 0);
        *reinterpret_cast<uint4*>(&sK[r * SQH])     = kh;
        *reinterpret_cast<uint4*>(&sK[r * SQH + 8]) = make_uint4(0, 0, 0, 0);
        *reinterpret_cast<uint4*>(&sV[r * 8])       = vh;
    }
    __syncthreads();

    // ---- preload Q A-frags ----
    uint32_t af[2][4];
    {
        const uint32_t a_lm = (uint32_t)((qb + (lane & 15)) * SQH + (lane >> 4) * 8);
#pragma unroll
        for (int mi = 0; mi < 2; mi++)
            ldsm4(af[mi][0], af[mi][1], af[mi][2], af[mi][3],
                  sQb + (a_lm + (uint32_t)(mi * 16 * SQH)) * 2);
    }

    float oacc[2][4];
#pragma unroll
    for (int mi = 0; mi < 2; mi++)
#pragma unroll
        for (int e = 0; e < 4; e++) oacc[mi][e] = 0.0f;
    float rs[2][2] = {{0.f, 0.f}, {0.f, 0.f}};

#pragma unroll
    for (int gb = 0; gb < 4; gb++) {
        uint32_t bf[8][2];
        const uint32_t b_lm = (uint32_t)((gb * 64 + (lane >> 4) * 8 + (lane & 7)) * SQH
                                         + ((lane >> 3) & 1) * 8);
#pragma unroll
        for (int p = 0; p < 4; p++)
            ldsm4(bf[2*p][0], bf[2*p][1], bf[2*p+1][0], bf[2*p+1][1],
                  sKb + (b_lm + (uint32_t)(p * 16 * SQH)) * 2);

        float sacc[2][8][4];
#pragma unroll
        for (int mi = 0; mi < 2; mi++)
#pragma unroll
            for (int nj = 0; nj < 8; nj++) {
#pragma unroll
                for (int e = 0; e < 4; e++) sacc[mi][nj][e] = 0.0f;
                mma_f16(sacc[mi][nj], af[mi], bf[nj]);
            }

        uint32_t pf[2][4][4];
#pragma unroll
        for (int mi = 0; mi < 2; mi++)
#pragma unroll
            for (int nj = 0; nj < 8; nj++) {
                float e0 = ex2f(sacc[mi][nj][0]);
                float e1 = ex2f(sacc[mi][nj][1]);
                float e2 = ex2f(sacc[mi][nj][2]);
                float e3 = ex2f(sacc[mi][nj][3]);
                rs[mi][0] += e0 + e1;
                rs[mi][1] += e2 + e3;
                const int p = nj >> 1;
                if ((nj & 1) == 0) {
                    pf[mi][p][0] = cvtpk(e1, e0);
                    pf[mi][p][1] = cvtpk(e3, e2);
                } else {
                    pf[mi][p][2] = cvtpk(e1, e0);
                    pf[mi][p][3] = cvtpk(e3, e2);
                }
            }

        uint32_t vf[4][2];
#pragma unroll
        for (int p = 0; p < 4; p++) {
            const uint32_t vaddr = sVb + (uint32_t)((gb * 64 + p * 16 + (lane & 15)) * 8) * 2;
            ldsm2t(vf[p][0], vf[p][1], vaddr);
        }

#pragma unroll
        for (int mi = 0; mi < 2; mi++)
#pragma unroll
            for (int p = 0; p < 4; p++)
                mma_f16(oacc[mi], pf[mi][p], vf[p]);
    }

#pragma unroll
    for (int mi = 0; mi < 2; mi++)
#pragma unroll
        for (int j = 0; j < 2; j++) {
            rs[mi][j] += __shfl_xor_sync(0xFFFFFFFF, rs[mi][j], 1);
            rs[mi][j] += __shfl_xor_sync(0xFFFFFFFF, rs[mi][j], 2);
        }

#pragma unroll
    for (int mi = 0; mi < 2; mi++) {
        const int r0 = qb + mi * 16 + (lane >> 2);
        const int c  = 2 * (lane & 3);
        const float inv0 = 1.0f / rs[mi][0];
        const float inv1 = 1.0f / rs[mi][1];
        *reinterpret_cast<__half2*>(&g_ah[(size_t)tk * DM + r0 * 8 + c]) =
            __floats2half2_rn(oacc[mi][0] * inv0, oacc[mi][1] * inv0);
        *reinterpret_cast<__half2*>(&g_ah[(size_t)tk * DM + (r0 + 8) * 8 + c]) =
            __floats2half2_rn(oacc[mi][2] * inv1, oacc[mi][3] * inv1);
    }
}

// ---------------------------------------------------------------------------
// Launch
// ---------------------------------------------------------------------------
extern "C" void kernel_launch(void* const* d_in, const int* in_sizes, int n_in,
                              void* d_out, int out_size)
{
    const float* x  = (const float*)d_in[0];
    // d_in[1] = phase_shift: cos^2+sin^2 cancels analytically; unused.
    const float* Wq = (const float*)d_in[2];
    const float* bq = (const float*)d_in[3];
    const float* Wk = (const float*)d_in[4];
    const float* bk = (const float*)d_in[5];
    const float* Wv = (const float*)d_in[6];
    const float* bv = (const float*)d_in[7];
    const float* Wo = (const float*)d_in[8];
    const float* bo = (const float*)d_in[9];
    float* out = (float*)d_out;

    __half *qh_p, *kh_p, *vh_p, *ah_p, *xh_p, *wt_p;
    cudaGetSymbolAddress((void**)&qh_p, g_qh);
    cudaGetSymbolAddress((void**)&kh_p, g_kh);
    cudaGetSymbolAddress((void**)&vh_p, g_vh);
    cudaGetSymbolAddress((void**)&ah_p, g_ah);
    cudaGetSymbolAddress((void**)&xh_p, g_xh);
    cudaGetSymbolAddress((void**)&wt_p, g_wth);

    constexpr int SM128 = NS * (A_H + 128 * SAH) * 2;   // 110592
    constexpr int SM64  = NS * (A_H + 64  * SAH) * 2;   // 82944
    cudaFuncSetAttribute((const void*)gemm_h<128, true>,
                         cudaFuncAttributeMaxDynamicSharedMemorySize, SM128);
    cudaFuncSetAttribute((const void*)gemm_h<64, false>,
                         cudaFuncAttributeMaxDynamicSharedMemorySize, SM64);

    const size_t WSZ = (size_t)DM * DM;
    const int nx4 = TOKENS * DM / 4;
    xcvt_kernel<<<(nx4 + 255) / 256, 256>>>(x, xh_p, nx4);
    wtrans_kernel<<<dim3(DM / 64, DM / 64, 4), 256>>>(Wq, Wk, Wv, Wo);

    dim3 gQKV(DM / 128, TOKENS / BM, 3);   // (16, 8, 3)
    gemm_h<128, true><<<gQKV, 256, SM128>>>(xh_p,
        wt_p, wt_p + WSZ, wt_p + 2 * WSZ,
        bq, bk, bv, qh_p, kh_p, vh_p);

    attn_kernel<<<TOKENS, 256>>>();

    dim3 gO(DM / 64, TOKENS / BM, 1);      // (32, 8, 1) = 256 CTAs
    gemm_h<64, false><<<gO, 256, SM64>>>(ah_p,
        wt_p + 3 * WSZ, wt_p + 3 * WSZ, wt_p + 3 * WSZ,
        bo, bo, bo, out, out, out);
}